// round 4
// baseline (speedup 1.0000x reference)
#include <cuda_runtime.h>
#include <cstdint>
#include <math.h>

// Problem dims (fixed by the reference)
#define BB 32
#define SS 512
#define DD 1024
#define HH 16
#define DK 64
#define FF 4096
#define MM (BB*SS)   // 16384 rows

// ---------------------------------------------------------------------------
// Scratch (static device arrays; no allocation APIs anywhere)
// ---------------------------------------------------------------------------
__device__ float g_q  [BB*HH*SS*DK];   // [B,H,S,dk], pre-scaled by 1/sqrt(dk)
__device__ float g_k  [BB*HH*SS*DK];
__device__ float g_v  [BB*HH*SS*DK];
__device__ float g_ctx[MM*DD];         // [B,S,D]
__device__ float g_tmp[MM*DD];         // attn_out, later ffn_out
__device__ float g_o1 [MM*DD];         // out1
__device__ float g_hid[(size_t)MM*FF]; // FFN hidden

// ---------------------------------------------------------------------------
// Helpers
// ---------------------------------------------------------------------------
__device__ __forceinline__ uint32_t f2tf32(float x) {
    uint32_t u;
    asm("cvt.rna.tf32.f32 %0, %1;" : "=r"(u) : "f"(x));
    return u;
}
__device__ __forceinline__ float tfr(float x) { return __uint_as_float(f2tf32(x)); }

__device__ __forceinline__ void mma8(float* c,
                                     uint32_t a0, uint32_t a1, uint32_t a2, uint32_t a3,
                                     uint32_t b0, uint32_t b1) {
    asm volatile(
        "mma.sync.aligned.m16n8k8.row.col.f32.tf32.tf32.f32 "
        "{%0,%1,%2,%3}, {%4,%5,%6,%7}, {%8,%9}, {%0,%1,%2,%3};\n"
        : "+f"(c[0]), "+f"(c[1]), "+f"(c[2]), "+f"(c[3])
        : "r"(a0), "r"(a1), "r"(a2), "r"(a3), "r"(b0), "r"(b1));
}

__device__ __forceinline__ float gelu_erf(float x) {
    return 0.5f * x * (1.0f + erff(x * 0.70710678118654752440f));
}

// ---------------------------------------------------------------------------
// Generic TF32 GEMM: C[M,N] = A[M,K] @ W[K,N] + bias, optional epilogues
//   EPI 0: plain (C row-major [M,N])
//   EPI 1: GELU(erf) then store
//   EPI 2: scatter into [B,H,S,dk] with post-bias scale alpha (QKV projections)
// Tiles: BM=128, BN=128, BK=16; 256 threads (8 warps, 4x2 warp grid, warp 32x64).
// ---------------------------------------------------------------------------
template <int EPI>
__global__ void __launch_bounds__(256)
gemm_tf32(const float* __restrict__ A, const float* __restrict__ W,
          const float* __restrict__ bias, float* __restrict__ C,
          int M, int N, int K, float alpha)
{
    __shared__ float sA[2][128][20];   // stride 20 => banks (4r+c): conflict-free frag loads
    __shared__ float sB[2][16][136];   // stride 136 => banks (8k+n): conflict-free

    const int tid  = threadIdx.x;
    const int m0   = blockIdx.y * 128;
    const int n0   = blockIdx.x * 128;
    const int warp = tid >> 5, lane = tid & 31;
    const int g    = lane >> 2, tg = lane & 3;
    const int warpM = warp & 3;   // 0..3 -> 32-row group
    const int warpN = warp >> 2;  // 0..1 -> 64-col group

    float acc[2][8][4];
#pragma unroll
    for (int a = 0; a < 2; a++)
#pragma unroll
        for (int b = 0; b < 8; b++)
#pragma unroll
            for (int c = 0; c < 4; c++) acc[a][b][c] = 0.f;

    const int nT = K / 16;

    // ---- prologue: tile 0 ----
    float4 ra[2], rb[2];
#pragma unroll
    for (int i = 0; i < 2; i++) {
        int s  = tid + i * 256;
        int r  = s >> 2,  c  = (s & 3)  * 4;
        int r2 = s >> 5,  c2 = (s & 31) * 4;
        ra[i] = *(const float4*)(A + (size_t)(m0 + r) * K + c);
        rb[i] = *(const float4*)(W + (size_t)r2 * N + n0 + c2);
    }
#pragma unroll
    for (int i = 0; i < 2; i++) {
        int s  = tid + i * 256;
        int r  = s >> 2,  c  = (s & 3)  * 4;
        int r2 = s >> 5,  c2 = (s & 31) * 4;
        *(float4*)&sA[0][r][c]   = make_float4(tfr(ra[i].x), tfr(ra[i].y), tfr(ra[i].z), tfr(ra[i].w));
        *(float4*)&sB[0][r2][c2] = make_float4(tfr(rb[i].x), tfr(rb[i].y), tfr(rb[i].z), tfr(rb[i].w));
    }
    __syncthreads();

    for (int t = 0; t < nT; t++) {
        const int buf = t & 1;
        const bool pf = (t + 1 < nT);
        if (pf) {
            int k0 = (t + 1) * 16;
#pragma unroll
            for (int i = 0; i < 2; i++) {
                int s  = tid + i * 256;
                int r  = s >> 2,  c  = (s & 3)  * 4;
                int r2 = s >> 5,  c2 = (s & 31) * 4;
                ra[i] = *(const float4*)(A + (size_t)(m0 + r) * K + k0 + c);
                rb[i] = *(const float4*)(W + (size_t)(k0 + r2) * N + n0 + c2);
            }
        }
        // ---- compute on buf ----
#pragma unroll
        for (int ks = 0; ks < 2; ks++) {
            uint32_t af[2][4];
#pragma unroll
            for (int mf = 0; mf < 2; mf++) {
                int r = warpM * 32 + mf * 16 + g;
                int c = ks * 8 + tg;
                af[mf][0] = __float_as_uint(sA[buf][r    ][c    ]);
                af[mf][1] = __float_as_uint(sA[buf][r + 8][c    ]);
                af[mf][2] = __float_as_uint(sA[buf][r    ][c + 4]);
                af[mf][3] = __float_as_uint(sA[buf][r + 8][c + 4]);
            }
#pragma unroll
            for (int nf = 0; nf < 8; nf++) {
                int n  = warpN * 64 + nf * 8 + g;
                int kk = ks * 8 + tg;
                uint32_t b0 = __float_as_uint(sB[buf][kk    ][n]);
                uint32_t b1 = __float_as_uint(sB[buf][kk + 4][n]);
                mma8(acc[0][nf], af[0][0], af[0][1], af[0][2], af[0][3], b0, b1);
                mma8(acc[1][nf], af[1][0], af[1][1], af[1][2], af[1][3], b0, b1);
            }
        }
        if (pf) {
#pragma unroll
            for (int i = 0; i < 2; i++) {
                int s  = tid + i * 256;
                int r  = s >> 2,  c  = (s & 3)  * 4;
                int r2 = s >> 5,  c2 = (s & 31) * 4;
                *(float4*)&sA[buf ^ 1][r][c]   = make_float4(tfr(ra[i].x), tfr(ra[i].y), tfr(ra[i].z), tfr(ra[i].w));
                *(float4*)&sB[buf ^ 1][r2][c2] = make_float4(tfr(rb[i].x), tfr(rb[i].y), tfr(rb[i].z), tfr(rb[i].w));
            }
            __syncthreads();
        }
    }

    // ---- epilogue ----
#pragma unroll
    for (int mf = 0; mf < 2; mf++) {
#pragma unroll
        for (int nf = 0; nf < 8; nf++) {
            int row = m0 + warpM * 32 + mf * 16 + g;
            int col = n0 + warpN * 64 + nf * 8 + tg * 2;
            float b0 = bias[col], b1 = bias[col + 1];
            float v0 = acc[mf][nf][0] + b0;
            float v1 = acc[mf][nf][1] + b1;
            float v2 = acc[mf][nf][2] + b0;
            float v3 = acc[mf][nf][3] + b1;
            if (EPI == 1) { v0 = gelu_erf(v0); v1 = gelu_erf(v1); v2 = gelu_erf(v2); v3 = gelu_erf(v3); }
            if (EPI == 2) {
                v0 *= alpha; v1 *= alpha; v2 *= alpha; v3 *= alpha;
                // (row,col) -> [B,H,S,dk]
                int bI = row >> 9, s = row & 511;
                int h  = col >> 6, d = col & 63;
                size_t base = (((size_t)(bI * HH + h)) * SS + s) * DK + d;
                C[base]     = v0;
                C[base + 1] = v1;
                C[base + 8 * DK]     = v2;   // row+8: s+8 -> +8*DK in this layout
                C[base + 8 * DK + 1] = v3;
            } else {
                size_t p0 = (size_t)row * N + col;
                C[p0]     = v0;
                C[p0 + 1] = v1;
                C[p0 + (size_t)8 * N]     = v2;
                C[p0 + (size_t)8 * N + 1] = v3;
            }
        }
    }
}

// ---------------------------------------------------------------------------
// Attention: one CTA per (b, h, 64-row q tile). Full scores row (S=512) in
// dynamic smem -> exact two-phase softmax, then P@V. TF32 mma throughout.
// ---------------------------------------------------------------------------
#define SS_STRIDE 516   // 516 % 32 == 4  -> banks (4q + c): conflict-free
#define SQ_STRIDE 68    //  68 % 32 == 4
#define SV_STRIDE 72    //  72 % 32 == 8  -> banks (8k + n): conflict-free
#define ATTN_SMEM ((64*SS_STRIDE + 64*SQ_STRIDE + 64*SV_STRIDE) * 4)

__global__ void __launch_bounds__(256)
attn_kernel(const float* __restrict__ adj, const int* __restrict__ mask)
{
    extern __shared__ float sm[];
    float* sS  = sm;                       // 64 x 516
    float* sQ  = sS + 64 * SS_STRIDE;      // 64 x 68 (tf32)
    float* sKV = sQ + 64 * SQ_STRIDE;      // 64 x 72 (tf32; K uses stride 68, V uses 72)
    __shared__ float sMaskB[SS];

    const int qt = blockIdx.x, h = blockIdx.y, b = blockIdx.z;
    const int q0 = qt * 64;
    const int tid = threadIdx.x;
    const int warp = tid >> 5, lane = tid & 31;
    const int g = lane >> 2, tg = lane & 3;

    const size_t headBase = ((size_t)(b * HH + h)) * SS * DK;

    // mask bias (depends only on key index)
    for (int i = tid; i < SS; i += 256)
        sMaskB[i] = -1e9f * (float)mask[b * SS + i];

    // load Q tile (already pre-scaled by 1/sqrt(dk))
#pragma unroll
    for (int i = 0; i < 4; i++) {
        int s = tid + i * 256;
        int r = s >> 4, c = (s & 15) * 4;
        float4 v = *(const float4*)(g_q + headBase + (size_t)(q0 + r) * DK + c);
        *(float4*)&sQ[r * SQ_STRIDE + c] = make_float4(tfr(v.x), tfr(v.y), tfr(v.z), tfr(v.w));
    }
    __syncthreads();

    // ---- phase 1: scores = Q K^T + maskbias + adj ----
    {
        const int warpQ = warp & 1;   // 32 q-rows
        const int warpK = warp >> 1;  // 16 k-cols
        for (int ch = 0; ch < 8; ch++) {
            // load K chunk (64 keys x 64 dims), stride 68
#pragma unroll
            for (int i = 0; i < 4; i++) {
                int s = tid + i * 256;
                int r = s >> 4, c = (s & 15) * 4;
                float4 v = *(const float4*)(g_k + headBase + (size_t)(ch * 64 + r) * DK + c);
                *(float4*)&sKV[r * SQ_STRIDE + c] = make_float4(tfr(v.x), tfr(v.y), tfr(v.z), tfr(v.w));
            }
            __syncthreads();

            float acc[2][2][4];
#pragma unroll
            for (int a = 0; a < 2; a++)
#pragma unroll
                for (int n = 0; n < 2; n++)
#pragma unroll
                    for (int c = 0; c < 4; c++) acc[a][n][c] = 0.f;

#pragma unroll
            for (int ks = 0; ks < 8; ks++) {
                uint32_t af[2][4];
#pragma unroll
                for (int mf = 0; mf < 2; mf++) {
                    int r = warpQ * 32 + mf * 16 + g;
                    int c = ks * 8 + tg;
                    af[mf][0] = __float_as_uint(sQ[r * SQ_STRIDE + c]);
                    af[mf][1] = __float_as_uint(sQ[(r + 8) * SQ_STRIDE + c]);
                    af[mf][2] = __float_as_uint(sQ[r * SQ_STRIDE + c + 4]);
                    af[mf][3] = __float_as_uint(sQ[(r + 8) * SQ_STRIDE + c + 4]);
                }
#pragma unroll
                for (int nf = 0; nf < 2; nf++) {
                    int n  = warpK * 16 + nf * 8 + g;   // key index (local)
                    int kk = ks * 8 + tg;               // dim index
                    uint32_t b0 = __float_as_uint(sKV[n * SQ_STRIDE + kk]);
                    uint32_t b1 = __float_as_uint(sKV[n * SQ_STRIDE + kk + 4]);
                    mma8(acc[0][nf], af[0][0], af[0][1], af[0][2], af[0][3], b0, b1);
                    mma8(acc[1][nf], af[1][0], af[1][1], af[1][2], af[1][3], b0, b1);
                }
            }
            // write scores with bias terms
#pragma unroll
            for (int mf = 0; mf < 2; mf++) {
#pragma unroll
                for (int nf = 0; nf < 2; nf++) {
                    int row = warpQ * 32 + mf * 16 + g;
                    int col = ch * 64 + warpK * 16 + nf * 8 + tg * 2;
                    const float* adj0 = adj + ((size_t)b * SS + q0 + row) * SS;
                    const float* adj1 = adj0 + 8 * SS;
                    sS[row * SS_STRIDE + col]           = acc[mf][nf][0] + sMaskB[col]     + adj0[col];
                    sS[row * SS_STRIDE + col + 1]       = acc[mf][nf][1] + sMaskB[col + 1] + adj0[col + 1];
                    sS[(row + 8) * SS_STRIDE + col]     = acc[mf][nf][2] + sMaskB[col]     + adj1[col];
                    sS[(row + 8) * SS_STRIDE + col + 1] = acc[mf][nf][3] + sMaskB[col + 1] + adj1[col + 1];
                }
            }
            __syncthreads();
        }
    }

    // ---- phase 2: softmax, each warp owns 8 rows ----
    {
        for (int r8 = 0; r8 < 8; r8++) {
            float* Sr = sS + (warp * 8 + r8) * SS_STRIDE;
            float mx = -3.4e38f;
            for (int j = lane; j < SS; j += 32) mx = fmaxf(mx, Sr[j]);
#pragma unroll
            for (int o = 16; o; o >>= 1) mx = fmaxf(mx, __shfl_xor_sync(0xffffffffu, mx, o));
            float sum = 0.f;
            for (int j = lane; j < SS; j += 32) {
                float e = __expf(Sr[j] - mx);
                Sr[j] = e;
                sum += e;
            }
#pragma unroll
            for (int o = 16; o; o >>= 1) sum += __shfl_xor_sync(0xffffffffu, sum, o);
            float inv = 1.f / sum;
            for (int j = lane; j < SS; j += 32) Sr[j] = tfr(Sr[j] * inv);
        }
        __syncthreads();
    }

    // ---- phase 3: ctx = P @ V ----
    {
        const int warpQ = warp & 1;   // 32 q-rows
        const int warpD = warp >> 1;  // 16 d-cols
        float o[2][2][4];
#pragma unroll
        for (int a = 0; a < 2; a++)
#pragma unroll
            for (int n = 0; n < 2; n++)
#pragma unroll
                for (int c = 0; c < 4; c++) o[a][n][c] = 0.f;

        for (int ch = 0; ch < 8; ch++) {
            // load V chunk (64 keys x 64 dims), stride 72
#pragma unroll
            for (int i = 0; i < 4; i++) {
                int s = tid + i * 256;
                int r = s >> 4, c = (s & 15) * 4;
                float4 v = *(const float4*)(g_v + headBase + (size_t)(ch * 64 + r) * DK + c);
                *(float4*)&sKV[r * SV_STRIDE + c] = make_float4(tfr(v.x), tfr(v.y), tfr(v.z), tfr(v.w));
            }
            __syncthreads();

#pragma unroll
            for (int ks = 0; ks < 8; ks++) {
                uint32_t af[2][4];
#pragma unroll
                for (int mf = 0; mf < 2; mf++) {
                    int r = warpQ * 32 + mf * 16 + g;
                    int c = ch * 64 + ks * 8 + tg;
                    af[mf][0] = __float_as_uint(sS[r * SS_STRIDE + c]);
                    af[mf][1] = __float_as_uint(sS[(r + 8) * SS_STRIDE + c]);
                    af[mf][2] = __float_as_uint(sS[r * SS_STRIDE + c + 4]);
                    af[mf][3] = __float_as_uint(sS[(r + 8) * SS_STRIDE + c + 4]);
                }
#pragma unroll
                for (int nf = 0; nf < 2; nf++) {
                    int n  = warpD * 16 + nf * 8 + g;  // dim
                    int kk = ks * 8 + tg;              // key (local)
                    uint32_t b0 = __float_as_uint(sKV[kk * SV_STRIDE + n]);
                    uint32_t b1 = __float_as_uint(sKV[(kk + 4) * SV_STRIDE + n]);
                    mma8(o[0][nf], af[0][0], af[0][1], af[0][2], af[0][3], b0, b1);
                    mma8(o[1][nf], af[1][0], af[1][1], af[1][2], af[1][3], b0, b1);
                }
            }
            __syncthreads();
        }

        // write ctx directly in [B,S,D] (D index = h*64 + d)
#pragma unroll
        for (int mf = 0; mf < 2; mf++) {
#pragma unroll
            for (int nf = 0; nf < 2; nf++) {
                int q = q0 + warpQ * 32 + mf * 16 + g;
                int d = warpD * 16 + nf * 8 + tg * 2;
                size_t base = ((size_t)b * SS + q) * DD + h * DK + d;
                g_ctx[base]     = o[mf][nf][0];
                g_ctx[base + 1] = o[mf][nf][1];
                g_ctx[base + 8 * DD]     = o[mf][nf][2];
                g_ctx[base + 8 * DD + 1] = o[mf][nf][3];
            }
        }
    }
}

// ---------------------------------------------------------------------------
// Residual + LayerNorm (torch semantics: unbiased std, / (std + eps))
// One CTA (256 thr) per row of 1024.
// ---------------------------------------------------------------------------
__global__ void __launch_bounds__(256)
ln_kernel(const float* __restrict__ a, const float* __restrict__ r,
          const float* __restrict__ gamma, const float* __restrict__ beta,
          float* __restrict__ out)
{
    __shared__ float red[8];
    const int row = blockIdx.x;
    const int tid = threadIdx.x;
    const int warp = tid >> 5, lane = tid & 31;

    float4 va = ((const float4*)(a + (size_t)row * DD))[tid];
    float4 vr = ((const float4*)(r + (size_t)row * DD))[tid];
    float v0 = va.x + vr.x, v1 = va.y + vr.y, v2 = va.z + vr.z, v3 = va.w + vr.w;

    float s = v0 + v1 + v2 + v3;
#pragma unroll
    for (int o = 16; o; o >>= 1) s += __shfl_xor_sync(0xffffffffu, s, o);
    if (lane == 0) red[warp] = s;
    __syncthreads();
    float tot = 0.f;
#pragma unroll
    for (int i = 0; i < 8; i++) tot += red[i];
    float mean = tot * (1.0f / 1024.0f);
    __syncthreads();

    float d0 = v0 - mean, d1 = v1 - mean, d2 = v2 - mean, d3 = v3 - mean;
    float sq = d0 * d0 + d1 * d1 + d2 * d2 + d3 * d3;
#pragma unroll
    for (int o = 16; o; o >>= 1) sq += __shfl_xor_sync(0xffffffffu, sq, o);
    if (lane == 0) red[warp] = sq;
    __syncthreads();
    float tot2 = 0.f;
#pragma unroll
    for (int i = 0; i < 8; i++) tot2 += red[i];
    float var = tot2 * (1.0f / 1023.0f);        // ddof=1
    float inv = 1.0f / (sqrtf(var) + 1e-6f);     // (std + eps)

    float4 gm = ((const float4*)gamma)[tid];
    float4 bt = ((const float4*)beta)[tid];
    float4 o4;
    o4.x = gm.x * d0 * inv + bt.x;
    o4.y = gm.y * d1 * inv + bt.y;
    o4.z = gm.z * d2 * inv + bt.z;
    o4.w = gm.w * d3 * inv + bt.w;
    ((float4*)(out + (size_t)row * DD))[tid] = o4;
}

// ---------------------------------------------------------------------------
// Launch
// ---------------------------------------------------------------------------
extern "C" void kernel_launch(void* const* d_in, const int* in_sizes, int n_in,
                              void* d_out, int out_size)
{
    const float* x    = (const float*)d_in[0];
    const int*   mask = (const int*)  d_in[1];
    const float* adj  = (const float*)d_in[2];
    // num_head may or may not be materialized as an input
    int base = (n_in > 3 && in_sizes[3] == 1) ? 4 : 3;
    const float* Wq = (const float*)d_in[base + 0];
    const float* bq = (const float*)d_in[base + 1];
    const float* Wk = (const float*)d_in[base + 2];
    const float* bk = (const float*)d_in[base + 3];
    const float* Wv = (const float*)d_in[base + 4];
    const float* bv = (const float*)d_in[base + 5];
    const float* Wo = (const float*)d_in[base + 6];
    const float* bo = (const float*)d_in[base + 7];
    const float* W1 = (const float*)d_in[base + 8];
    const float* b1 = (const float*)d_in[base + 9];
    const float* W2 = (const float*)d_in[base + 10];
    const float* b2 = (const float*)d_in[base + 11];
    const float* gm = (const float*)d_in[base + 12];
    const float* bt = (const float*)d_in[base + 13];
    float* out = (float*)d_out;

    float *q, *k, *v, *ctx, *tmp, *o1, *hid;
    cudaGetSymbolAddress((void**)&q,   g_q);
    cudaGetSymbolAddress((void**)&k,   g_k);
    cudaGetSymbolAddress((void**)&v,   g_v);
    cudaGetSymbolAddress((void**)&ctx, g_ctx);
    cudaGetSymbolAddress((void**)&tmp, g_tmp);
    cudaGetSymbolAddress((void**)&o1,  g_o1);
    cudaGetSymbolAddress((void**)&hid, g_hid);

    dim3 gD(DD / 128, MM / 128);   // (8,128)
    dim3 gF(FF / 128, MM / 128);   // (32,128)

    // QKV projections (Q pre-scaled by 1/sqrt(64) = 0.125)
    gemm_tf32<2><<<gD, 256>>>(x, Wq, bq, q, MM, DD, DD, 0.125f);
    gemm_tf32<2><<<gD, 256>>>(x, Wk, bk, k, MM, DD, DD, 1.0f);
    gemm_tf32<2><<<gD, 256>>>(x, Wv, bv, v, MM, DD, DD, 1.0f);

    cudaFuncSetAttribute(attn_kernel, cudaFuncAttributeMaxDynamicSharedMemorySize, ATTN_SMEM);
    attn_kernel<<<dim3(SS / 64, HH, BB), 256, ATTN_SMEM>>>(adj, mask);

    gemm_tf32<0><<<gD, 256>>>(ctx, Wo, bo, tmp, MM, DD, DD, 1.0f);
    ln_kernel<<<MM, 256>>>(x, tmp, gm, bt, o1);

    gemm_tf32<1><<<gF, 256>>>(o1, W1, b1, hid, MM, FF, DD, 1.0f);
    gemm_tf32<0><<<gD, 256>>>(hid, W2, b2, tmp, MM, DD, FF, 1.0f);
    ln_kernel<<<MM, 256>>>(o1, tmp, gm, bt, out);
}

// round 6
// speedup vs baseline: 1.0059x; 1.0059x over previous
#include <cuda_runtime.h>
#include <cstdint>
#include <math.h>

// Problem dims (fixed by the reference)
#define BB 32
#define SS 512
#define DD 1024
#define HH 16
#define DK 64
#define FF 4096
#define MM (BB*SS)   // 16384 rows

// ---------------------------------------------------------------------------
// Scratch (static device arrays; no allocation APIs anywhere)
// ---------------------------------------------------------------------------
__device__ float g_q  [BB*HH*SS*DK];   // [B,H,S,dk], pre-scaled by 1/sqrt(dk)
__device__ float g_k  [BB*HH*SS*DK];
__device__ float g_v  [BB*HH*SS*DK];
__device__ float g_ctx[MM*DD];         // [B,S,D]
__device__ float g_tmp[MM*DD];         // attn_out, later ffn_out
__device__ float g_o1 [MM*DD];         // out1
__device__ float g_hid[(size_t)MM*FF]; // FFN hidden

// ---------------------------------------------------------------------------
// Helpers
// ---------------------------------------------------------------------------
__device__ __forceinline__ uint32_t f2tf32(float x) {
    uint32_t u;
    asm("cvt.rna.tf32.f32 %0, %1;" : "=r"(u) : "f"(x));
    return u;
}
__device__ __forceinline__ float tfr(float x) { return __uint_as_float(f2tf32(x)); }

__device__ __forceinline__ void mma8(float* c,
                                     uint32_t a0, uint32_t a1, uint32_t a2, uint32_t a3,
                                     uint32_t b0, uint32_t b1) {
    asm volatile(
        "mma.sync.aligned.m16n8k8.row.col.f32.tf32.tf32.f32 "
        "{%0,%1,%2,%3}, {%4,%5,%6,%7}, {%8,%9}, {%0,%1,%2,%3};\n"
        : "+f"(c[0]), "+f"(c[1]), "+f"(c[2]), "+f"(c[3])
        : "r"(a0), "r"(a1), "r"(a2), "r"(a3), "r"(b0), "r"(b1));
}

__device__ __forceinline__ float gelu_erf(float x) {
    return 0.5f * x * (1.0f + erff(x * 0.70710678118654752440f));
}

// ---------------------------------------------------------------------------
// TF32 GEMM: C[M,N] = A[M,K] @ W[K,N] + bias, optional epilogues
//   EPI 0: plain (C row-major [M,N])
//   EPI 1: GELU(erf) then store
//   EPI 2: scatter into [B,H,S,dk] with post-bias scale alpha (QKV projections)
// Tiles: BM=128, BN=128, BK=16. 128 threads = 4 warps in a 2x2 grid,
// each warp owns a 64x64 sub-tile (acc = 128 regs) -> halves smem traffic
// per MAC vs 32x64 warp tiles; 2 CTAs/SM overlap LDS with MMA.
// ---------------------------------------------------------------------------
template <int EPI>
__global__ void __launch_bounds__(128)
gemm_tf32(const float* __restrict__ A, const float* __restrict__ W,
          const float* __restrict__ bias, float* __restrict__ C,
          int M, int N, int K, float alpha)
{
    __shared__ float sA[2][128][20];   // stride 20 => banks (4r+c): conflict-free frag loads
    __shared__ float sB[2][16][136];   // stride 136 => banks (8k+n): conflict-free

    const int tid  = threadIdx.x;
    const int m0   = blockIdx.y * 128;
    const int n0   = blockIdx.x * 128;
    const int warp = tid >> 5, lane = tid & 31;
    const int g    = lane >> 2, tg = lane & 3;
    const int warpM = warp & 1;   // 0..1 -> 64-row group
    const int warpN = warp >> 1;  // 0..1 -> 64-col group

    float acc[4][8][4];
#pragma unroll
    for (int a = 0; a < 4; a++)
#pragma unroll
        for (int b = 0; b < 8; b++)
#pragma unroll
            for (int c = 0; c < 4; c++) acc[a][b][c] = 0.f;

    const int nT = K / 16;

    // ---- prologue: tile 0 ----
    float4 ra[4], rb[4];
#pragma unroll
    for (int i = 0; i < 4; i++) {
        int s  = tid + i * 128;
        int r  = s >> 2,  c  = (s & 3)  * 4;   // A: 128 rows x 16 cols
        int r2 = s >> 5,  c2 = (s & 31) * 4;   // B: 16 rows x 128 cols
        ra[i] = *(const float4*)(A + (size_t)(m0 + r) * K + c);
        rb[i] = *(const float4*)(W + (size_t)r2 * N + n0 + c2);
    }
#pragma unroll
    for (int i = 0; i < 4; i++) {
        int s  = tid + i * 128;
        int r  = s >> 2,  c  = (s & 3)  * 4;
        int r2 = s >> 5,  c2 = (s & 31) * 4;
        *(float4*)&sA[0][r][c]   = make_float4(tfr(ra[i].x), tfr(ra[i].y), tfr(ra[i].z), tfr(ra[i].w));
        *(float4*)&sB[0][r2][c2] = make_float4(tfr(rb[i].x), tfr(rb[i].y), tfr(rb[i].z), tfr(rb[i].w));
    }
    __syncthreads();

    for (int t = 0; t < nT; t++) {
        const int buf = t & 1;
        const bool pf = (t + 1 < nT);
        if (pf) {
            int k0 = (t + 1) * 16;
#pragma unroll
            for (int i = 0; i < 4; i++) {
                int s  = tid + i * 128;
                int r  = s >> 2,  c  = (s & 3)  * 4;
                int r2 = s >> 5,  c2 = (s & 31) * 4;
                ra[i] = *(const float4*)(A + (size_t)(m0 + r) * K + k0 + c);
                rb[i] = *(const float4*)(W + (size_t)(k0 + r2) * N + n0 + c2);
            }
        }
        // ---- compute on buf ----
#pragma unroll
        for (int ks = 0; ks < 2; ks++) {
            uint32_t af[4][4];
#pragma unroll
            for (int mf = 0; mf < 4; mf++) {
                int r = warpM * 64 + mf * 16 + g;
                int c = ks * 8 + tg;
                af[mf][0] = __float_as_uint(sA[buf][r    ][c    ]);
                af[mf][1] = __float_as_uint(sA[buf][r + 8][c    ]);
                af[mf][2] = __float_as_uint(sA[buf][r    ][c + 4]);
                af[mf][3] = __float_as_uint(sA[buf][r + 8][c + 4]);
            }
#pragma unroll
            for (int nf = 0; nf < 8; nf++) {
                int n  = warpN * 64 + nf * 8 + g;
                int kk = ks * 8 + tg;
                uint32_t b0 = __float_as_uint(sB[buf][kk    ][n]);
                uint32_t b1 = __float_as_uint(sB[buf][kk + 4][n]);
#pragma unroll
                for (int mf = 0; mf < 4; mf++)
                    mma8(acc[mf][nf], af[mf][0], af[mf][1], af[mf][2], af[mf][3], b0, b1);
            }
        }
        if (pf) {
#pragma unroll
            for (int i = 0; i < 4; i++) {
                int s  = tid + i * 128;
                int r  = s >> 2,  c  = (s & 3)  * 4;
                int r2 = s >> 5,  c2 = (s & 31) * 4;
                *(float4*)&sA[buf ^ 1][r][c]   = make_float4(tfr(ra[i].x), tfr(ra[i].y), tfr(ra[i].z), tfr(ra[i].w));
                *(float4*)&sB[buf ^ 1][r2][c2] = make_float4(tfr(rb[i].x), tfr(rb[i].y), tfr(rb[i].z), tfr(rb[i].w));
            }
            __syncthreads();
        }
    }

    // ---- epilogue ----
#pragma unroll
    for (int mf = 0; mf < 4; mf++) {
#pragma unroll
        for (int nf = 0; nf < 8; nf++) {
            int row = m0 + warpM * 64 + mf * 16 + g;
            int col = n0 + warpN * 64 + nf * 8 + tg * 2;
            float b0 = bias[col], b1 = bias[col + 1];
            float v0 = acc[mf][nf][0] + b0;
            float v1 = acc[mf][nf][1] + b1;
            float v2 = acc[mf][nf][2] + b0;
            float v3 = acc[mf][nf][3] + b1;
            if (EPI == 1) { v0 = gelu_erf(v0); v1 = gelu_erf(v1); v2 = gelu_erf(v2); v3 = gelu_erf(v3); }
            if (EPI == 2) {
                v0 *= alpha; v1 *= alpha; v2 *= alpha; v3 *= alpha;
                // (row,col) -> [B,H,S,dk]; 128-row tiles never cross a batch boundary
                int bI = row >> 9, s = row & 511;
                int h  = col >> 6, d = col & 63;
                size_t base = (((size_t)(bI * HH + h)) * SS + s) * DK + d;
                C[base]     = v0;
                C[base + 1] = v1;
                C[base + 8 * DK]     = v2;   // row+8: s+8 -> +8*DK in this layout
                C[base + 8 * DK + 1] = v3;
            } else {
                size_t p0 = (size_t)row * N + col;
                C[p0]     = v0;
                C[p0 + 1] = v1;
                C[p0 + (size_t)8 * N]     = v2;
                C[p0 + (size_t)8 * N + 1] = v3;
            }
        }
    }
}

// ---------------------------------------------------------------------------
// Attention: one CTA per (b, h, 64-row q tile). Full scores row (S=512) in
// dynamic smem -> exact two-phase softmax, then P@V. TF32 mma throughout.
// ---------------------------------------------------------------------------
#define SS_STRIDE 516   // 516 % 32 == 4  -> banks (4q + c): conflict-free
#define SQ_STRIDE 68    //  68 % 32 == 4
#define SV_STRIDE 72    //  72 % 32 == 8  -> banks (8k + n): conflict-free
#define ATTN_SMEM ((64*SS_STRIDE + 64*SQ_STRIDE + 64*SV_STRIDE) * 4)

__global__ void __launch_bounds__(256)
attn_kernel(const float* __restrict__ adj, const int* __restrict__ mask)
{
    extern __shared__ float sm[];
    float* sS  = sm;                       // 64 x 516
    float* sQ  = sS + 64 * SS_STRIDE;      // 64 x 68 (tf32)
    float* sKV = sQ + 64 * SQ_STRIDE;      // 64 x 72 (tf32; K uses stride 68, V uses 72)
    __shared__ float sMaskB[SS];

    const int qt = blockIdx.x, h = blockIdx.y, b = blockIdx.z;
    const int q0 = qt * 64;
    const int tid = threadIdx.x;
    const int warp = tid >> 5, lane = tid & 31;
    const int g = lane >> 2, tg = lane & 3;

    const size_t headBase = ((size_t)(b * HH + h)) * SS * DK;

    // mask bias (depends only on key index)
    for (int i = tid; i < SS; i += 256)
        sMaskB[i] = -1e9f * (float)mask[b * SS + i];

    // load Q tile (already pre-scaled by 1/sqrt(dk))
#pragma unroll
    for (int i = 0; i < 4; i++) {
        int s = tid + i * 256;
        int r = s >> 4, c = (s & 15) * 4;
        float4 v = *(const float4*)(g_q + headBase + (size_t)(q0 + r) * DK + c);
        *(float4*)&sQ[r * SQ_STRIDE + c] = make_float4(tfr(v.x), tfr(v.y), tfr(v.z), tfr(v.w));
    }
    __syncthreads();

    // ---- phase 1: scores = Q K^T + maskbias + adj ----
    {
        const int warpQ = warp & 1;   // 32 q-rows
        const int warpK = warp >> 1;  // 16 k-cols
        for (int ch = 0; ch < 8; ch++) {
            // load K chunk (64 keys x 64 dims), stride 68
#pragma unroll
            for (int i = 0; i < 4; i++) {
                int s = tid + i * 256;
                int r = s >> 4, c = (s & 15) * 4;
                float4 v = *(const float4*)(g_k + headBase + (size_t)(ch * 64 + r) * DK + c);
                *(float4*)&sKV[r * SQ_STRIDE + c] = make_float4(tfr(v.x), tfr(v.y), tfr(v.z), tfr(v.w));
            }
            __syncthreads();

            float acc[2][2][4];
#pragma unroll
            for (int a = 0; a < 2; a++)
#pragma unroll
                for (int n = 0; n < 2; n++)
#pragma unroll
                    for (int c = 0; c < 4; c++) acc[a][n][c] = 0.f;

#pragma unroll
            for (int ks = 0; ks < 8; ks++) {
                uint32_t af[2][4];
#pragma unroll
                for (int mf = 0; mf < 2; mf++) {
                    int r = warpQ * 32 + mf * 16 + g;
                    int c = ks * 8 + tg;
                    af[mf][0] = __float_as_uint(sQ[r * SQ_STRIDE + c]);
                    af[mf][1] = __float_as_uint(sQ[(r + 8) * SQ_STRIDE + c]);
                    af[mf][2] = __float_as_uint(sQ[r * SQ_STRIDE + c + 4]);
                    af[mf][3] = __float_as_uint(sQ[(r + 8) * SQ_STRIDE + c + 4]);
                }
#pragma unroll
                for (int nf = 0; nf < 2; nf++) {
                    int n  = warpK * 16 + nf * 8 + g;   // key index (local)
                    int kk = ks * 8 + tg;               // dim index
                    uint32_t b0 = __float_as_uint(sKV[n * SQ_STRIDE + kk]);
                    uint32_t b1 = __float_as_uint(sKV[n * SQ_STRIDE + kk + 4]);
                    mma8(acc[0][nf], af[0][0], af[0][1], af[0][2], af[0][3], b0, b1);
                    mma8(acc[1][nf], af[1][0], af[1][1], af[1][2], af[1][3], b0, b1);
                }
            }
            // write scores with bias terms
#pragma unroll
            for (int mf = 0; mf < 2; mf++) {
#pragma unroll
                for (int nf = 0; nf < 2; nf++) {
                    int row = warpQ * 32 + mf * 16 + g;
                    int col = ch * 64 + warpK * 16 + nf * 8 + tg * 2;
                    const float* adj0 = adj + ((size_t)b * SS + q0 + row) * SS;
                    const float* adj1 = adj0 + 8 * SS;
                    sS[row * SS_STRIDE + col]           = acc[mf][nf][0] + sMaskB[col]     + adj0[col];
                    sS[row * SS_STRIDE + col + 1]       = acc[mf][nf][1] + sMaskB[col + 1] + adj0[col + 1];
                    sS[(row + 8) * SS_STRIDE + col]     = acc[mf][nf][2] + sMaskB[col]     + adj1[col];
                    sS[(row + 8) * SS_STRIDE + col + 1] = acc[mf][nf][3] + sMaskB[col + 1] + adj1[col + 1];
                }
            }
            __syncthreads();
        }
    }

    // ---- phase 2: softmax, each warp owns 8 rows ----
    {
        for (int r8 = 0; r8 < 8; r8++) {
            float* Sr = sS + (warp * 8 + r8) * SS_STRIDE;
            float mx = -3.4e38f;
            for (int j = lane; j < SS; j += 32) mx = fmaxf(mx, Sr[j]);
#pragma unroll
            for (int o = 16; o; o >>= 1) mx = fmaxf(mx, __shfl_xor_sync(0xffffffffu, mx, o));
            float sum = 0.f;
            for (int j = lane; j < SS; j += 32) {
                float e = __expf(Sr[j] - mx);
                Sr[j] = e;
                sum += e;
            }
#pragma unroll
            for (int o = 16; o; o >>= 1) sum += __shfl_xor_sync(0xffffffffu, sum, o);
            float inv = 1.f / sum;
            for (int j = lane; j < SS; j += 32) Sr[j] = tfr(Sr[j] * inv);
        }
        __syncthreads();
    }

    // ---- phase 3: ctx = P @ V ----
    {
        const int warpQ = warp & 1;   // 32 q-rows
        const int warpD = warp >> 1;  // 16 d-cols
        float o[2][2][4];
#pragma unroll
        for (int a = 0; a < 2; a++)
#pragma unroll
            for (int n = 0; n < 2; n++)
#pragma unroll
                for (int c = 0; c < 4; c++) o[a][n][c] = 0.f;

        for (int ch = 0; ch < 8; ch++) {
            // load V chunk (64 keys x 64 dims), stride 72
#pragma unroll
            for (int i = 0; i < 4; i++) {
                int s = tid + i * 256;
                int r = s >> 4, c = (s & 15) * 4;
                float4 v = *(const float4*)(g_v + headBase + (size_t)(ch * 64 + r) * DK + c);
                *(float4*)&sKV[r * SV_STRIDE + c] = make_float4(tfr(v.x), tfr(v.y), tfr(v.z), tfr(v.w));
            }
            __syncthreads();

#pragma unroll
            for (int ks = 0; ks < 8; ks++) {
                uint32_t af[2][4];
#pragma unroll
                for (int mf = 0; mf < 2; mf++) {
                    int r = warpQ * 32 + mf * 16 + g;
                    int c = ch * 64 + ks * 8 + tg;
                    af[mf][0] = __float_as_uint(sS[r * SS_STRIDE + c]);
                    af[mf][1] = __float_as_uint(sS[(r + 8) * SS_STRIDE + c]);
                    af[mf][2] = __float_as_uint(sS[r * SS_STRIDE + c + 4]);
                    af[mf][3] = __float_as_uint(sS[(r + 8) * SS_STRIDE + c + 4]);
                }
#pragma unroll
                for (int nf = 0; nf < 2; nf++) {
                    int n  = warpD * 16 + nf * 8 + g;  // dim
                    int kk = ks * 8 + tg;              // key (local)
                    uint32_t b0 = __float_as_uint(sKV[kk * SV_STRIDE + n]);
                    uint32_t b1 = __float_as_uint(sKV[(kk + 4) * SV_STRIDE + n]);
                    mma8(o[0][nf], af[0][0], af[0][1], af[0][2], af[0][3], b0, b1);
                    mma8(o[1][nf], af[1][0], af[1][1], af[1][2], af[1][3], b0, b1);
                }
            }
            __syncthreads();
        }

        // write ctx directly in [B,S,D] (D index = h*64 + d)
#pragma unroll
        for (int mf = 0; mf < 2; mf++) {
#pragma unroll
            for (int nf = 0; nf < 2; nf++) {
                int q = q0 + warpQ * 32 + mf * 16 + g;
                int d = warpD * 16 + nf * 8 + tg * 2;
                size_t base = ((size_t)b * SS + q) * DD + h * DK + d;
                g_ctx[base]     = o[mf][nf][0];
                g_ctx[base + 1] = o[mf][nf][1];
                g_ctx[base + 8 * DD]     = o[mf][nf][2];
                g_ctx[base + 8 * DD + 1] = o[mf][nf][3];
            }
        }
    }
}

// ---------------------------------------------------------------------------
// Residual + LayerNorm (torch semantics: unbiased std, / (std + eps))
// One CTA (256 thr) per row of 1024.
// ---------------------------------------------------------------------------
__global__ void __launch_bounds__(256)
ln_kernel(const float* __restrict__ a, const float* __restrict__ r,
          const float* __restrict__ gamma, const float* __restrict__ beta,
          float* __restrict__ out)
{
    __shared__ float red[8];
    const int row = blockIdx.x;
    const int tid = threadIdx.x;
    const int warp = tid >> 5, lane = tid & 31;

    float4 va = ((const float4*)(a + (size_t)row * DD))[tid];
    float4 vr = ((const float4*)(r + (size_t)row * DD))[tid];
    float v0 = va.x + vr.x, v1 = va.y + vr.y, v2 = va.z + vr.z, v3 = va.w + vr.w;

    float s = v0 + v1 + v2 + v3;
#pragma unroll
    for (int o = 16; o; o >>= 1) s += __shfl_xor_sync(0xffffffffu, s, o);
    if (lane == 0) red[warp] = s;
    __syncthreads();
    float tot = 0.f;
#pragma unroll
    for (int i = 0; i < 8; i++) tot += red[i];
    float mean = tot * (1.0f / 1024.0f);
    __syncthreads();

    float d0 = v0 - mean, d1 = v1 - mean, d2 = v2 - mean, d3 = v3 - mean;
    float sq = d0 * d0 + d1 * d1 + d2 * d2 + d3 * d3;
#pragma unroll
    for (int o = 16; o; o >>= 1) sq += __shfl_xor_sync(0xffffffffu, sq, o);
    if (lane == 0) red[warp] = sq;
    __syncthreads();
    float tot2 = 0.f;
#pragma unroll
    for (int i = 0; i < 8; i++) tot2 += red[i];
    float var = tot2 * (1.0f / 1023.0f);        // ddof=1
    float inv = 1.0f / (sqrtf(var) + 1e-6f);     // (std + eps)

    float4 gm = ((const float4*)gamma)[tid];
    float4 bt = ((const float4*)beta)[tid];
    float4 o4;
    o4.x = gm.x * d0 * inv + bt.x;
    o4.y = gm.y * d1 * inv + bt.y;
    o4.z = gm.z * d2 * inv + bt.z;
    o4.w = gm.w * d3 * inv + bt.w;
    ((float4*)(out + (size_t)row * DD))[tid] = o4;
}

// ---------------------------------------------------------------------------
// Launch
// ---------------------------------------------------------------------------
extern "C" void kernel_launch(void* const* d_in, const int* in_sizes, int n_in,
                              void* d_out, int out_size)
{
    const float* x    = (const float*)d_in[0];
    const int*   mask = (const int*)  d_in[1];
    const float* adj  = (const float*)d_in[2];
    // num_head may or may not be materialized as an input
    int base = (n_in > 3 && in_sizes[3] == 1) ? 4 : 3;
    const float* Wq = (const float*)d_in[base + 0];
    const float* bq = (const float*)d_in[base + 1];
    const float* Wk = (const float*)d_in[base + 2];
    const float* bk = (const float*)d_in[base + 3];
    const float* Wv = (const float*)d_in[base + 4];
    const float* bv = (const float*)d_in[base + 5];
    const float* Wo = (const float*)d_in[base + 6];
    const float* bo = (const float*)d_in[base + 7];
    const float* W1 = (const float*)d_in[base + 8];
    const float* b1 = (const float*)d_in[base + 9];
    const float* W2 = (const float*)d_in[base + 10];
    const float* b2 = (const float*)d_in[base + 11];
    const float* gm = (const float*)d_in[base + 12];
    const float* bt = (const float*)d_in[base + 13];
    float* out = (float*)d_out;

    float *q, *k, *v, *ctx, *tmp, *o1, *hid;
    cudaGetSymbolAddress((void**)&q,   g_q);
    cudaGetSymbolAddress((void**)&k,   g_k);
    cudaGetSymbolAddress((void**)&v,   g_v);
    cudaGetSymbolAddress((void**)&ctx, g_ctx);
    cudaGetSymbolAddress((void**)&tmp, g_tmp);
    cudaGetSymbolAddress((void**)&o1,  g_o1);
    cudaGetSymbolAddress((void**)&hid, g_hid);

    dim3 gD(DD / 128, MM / 128);   // (8,128)
    dim3 gF(FF / 128, MM / 128);   // (32,128)

    // QKV projections (Q pre-scaled by 1/sqrt(64) = 0.125)
    gemm_tf32<2><<<gD, 128>>>(x, Wq, bq, q, MM, DD, DD, 0.125f);
    gemm_tf32<2><<<gD, 128>>>(x, Wk, bk, k, MM, DD, DD, 1.0f);
    gemm_tf32<2><<<gD, 128>>>(x, Wv, bv, v, MM, DD, DD, 1.0f);

    cudaFuncSetAttribute(attn_kernel, cudaFuncAttributeMaxDynamicSharedMemorySize, ATTN_SMEM);
    attn_kernel<<<dim3(SS / 64, HH, BB), 256, ATTN_SMEM>>>(adj, mask);

    gemm_tf32<0><<<gD, 128>>>(ctx, Wo, bo, tmp, MM, DD, DD, 1.0f);
    ln_kernel<<<MM, 256>>>(x, tmp, gm, bt, o1);

    gemm_tf32<1><<<gF, 128>>>(o1, W1, b1, hid, MM, FF, DD, 1.0f);
    gemm_tf32<0><<<gD, 128>>>(hid, W2, b2, tmp, MM, DD, FF, 1.0f);
    ln_kernel<<<MM, 256>>>(o1, tmp, gm, bt, out);
}